// round 15
// baseline (speedup 1.0000x reference)
#include <cuda_runtime.h>

#define EPSF 1e-10f
#define MAXP 4096

static __device__ double g_partials[MAXP];
static __device__ unsigned g_count;   // zero-init; reset by last block each launch

__global__ void __launch_bounds__(256) loss_k(
    const float* __restrict__ preds,
    const long long* __restrict__ labs,
    const int* __restrict__ cen,
    int N, int rows, float* __restrict__ out)
{
    const int tid = threadIdx.x;
    const int g = blockIdx.x * blockDim.x + tid;   // pair index
    double local = 0.0;

    const int npairs = rows >> 1;
    if (g < npairs) {
        const int r0 = 2 * g;
        const int r1 = 2 * g + 1;

        // independent metadata for both rows (N even -> same mod half)
        const int c0 = cen[r0];
        const int c1 = cen[r1];
        const long long ls0 = labs[r0];
        const long long ls1 = labs[r1];
        const bool hi = (r0 >= N);
        const long long l00 = hi ? labs[r0 - N] : ls0;
        const long long l01 = hi ? labs[r1 - N] : ls1;

        const float* p0 = preds + (size_t)r0 * 100;
        const float* p1 = p0 + 100;

        // uncensored gathers (independent, issue early)
        if (c0 == 0) local += (double)__logf(__ldg(p0 + (int)ls0) + EPSF);
        if (c1 == 0) local += (double)__logf(__ldg(p1 + (int)ls1) + EPSF);

        const bool d0 = (c0 == 1);
        const bool d1 = (c1 == 1);
        if (d0 | d1) {
            // per-row window params: read shorter of suffix/prefix
            const int t10 = (int)l00 + 1;                 // 1..100
            const int t11 = (int)l01 + 1;
            const bool sf0 = (t10 > 50);
            const bool sf1 = (t11 > 50);
            const int lo0 = sf0 ? (t10 >> 2) : 0;
            const int lo1 = sf1 ? (t11 >> 2) : 0;
            const int hi0 = sf0 ? 25 : ((t10 + 3) >> 2);
            const int hi1 = sf1 ? 25 : ((t11 + 3) >> 2);
            const int rm0 = t10 & 3;
            const int rm1 = t11 & 3;

            const float4* q0 = (const float4*)p0;   // 400B rows -> 16B aligned
            const float4* q1 = (const float4*)p1;

            float a0 = 0.f, a1 = 0.f;
            #pragma unroll
            for (int k = 0; k < 13; ++k) {
                const int j0 = lo0 + k;
                const int j1 = lo1 + k;
                float4 u0 = (d0 && j0 < hi0) ? __ldg(q0 + j0)
                                             : make_float4(0.f, 0.f, 0.f, 0.f);
                float4 u1 = (d1 && j1 < hi1) ? __ldg(q1 + j1)
                                             : make_float4(0.f, 0.f, 0.f, 0.f);
                // row 0 edge masks
                if (sf0) {
                    if (j0 == lo0 && rm0) {
                        if (rm0 > 0) u0.x = 0.f;
                        if (rm0 > 1) u0.y = 0.f;
                        if (rm0 > 2) u0.z = 0.f;
                    }
                } else if (j0 == hi0 - 1 && rm0) {
                    if (rm0 < 2) u0.y = 0.f;
                    if (rm0 < 3) u0.z = 0.f;
                    u0.w = 0.f;
                }
                // row 1 edge masks
                if (sf1) {
                    if (j1 == lo1 && rm1) {
                        if (rm1 > 0) u1.x = 0.f;
                        if (rm1 > 1) u1.y = 0.f;
                        if (rm1 > 2) u1.z = 0.f;
                    }
                } else if (j1 == hi1 - 1 && rm1) {
                    if (rm1 < 2) u1.y = 0.f;
                    if (rm1 < 3) u1.z = 0.f;
                    u1.w = 0.f;
                }
                a0 += (u0.x + u0.y) + (u0.z + u0.w);
                a1 += (u1.x + u1.y) + (u1.z + u1.w);
            }
            if (d0) {
                const float s = sf0 ? a0 : fmaxf(1.0f - a0, 0.0f);
                local += 0.5 * (double)__logf(s + EPSF);
            }
            if (d1) {
                const float s = sf1 ? a1 : fmaxf(1.0f - a1, 0.0f);
                local += 0.5 * (double)__logf(s + EPSF);
            }
        }
    }

    // block reduction (doubles)
    #pragma unroll
    for (int o = 16; o; o >>= 1)
        local += __shfl_down_sync(0xffffffffu, local, o);

    __shared__ double wsum[8];
    const int lane = tid & 31;
    const int wib = tid >> 5;
    if (lane == 0) wsum[wib] = local;
    __syncthreads();

    if (wib == 0) {
        double v = (lane < 8) ? wsum[lane] : 0.0;
        #pragma unroll
        for (int o = 4; o; o >>= 1)
            v += __shfl_down_sync(0xffffffffu, v, o);
        if (lane == 0) g_partials[blockIdx.x] = v;
    }

    // last-block-done final reduction (no second kernel)
    __shared__ bool isLast;
    if (tid == 0) {
        __threadfence();
        unsigned c = atomicAdd(&g_count, 1u);
        isLast = (c == gridDim.x - 1);
    }
    __syncthreads();

    if (isLast) {   // block-uniform
        double v = 0.0;
        for (int k = tid; k < (int)gridDim.x; k += blockDim.x)
            v += g_partials[k];
        #pragma unroll
        for (int o = 16; o; o >>= 1)
            v += __shfl_down_sync(0xffffffffu, v, o);
        if (lane == 0) wsum[wib] = v;
        __syncthreads();
        if (tid == 0) {
            double t = 0.0;
            #pragma unroll
            for (int w = 0; w < 8; ++w) t += wsum[w];
            *out = (float)(-t / (double)N);
            g_count = 0;                      // reset for next graph replay
        }
    }
}

extern "C" void kernel_launch(void* const* d_in, const int* in_sizes, int n_in,
                              void* d_out, int out_size)
{
    const float* preds = (const float*)d_in[0];        // [2, N, 100] f32
    const long long* labs = (const long long*)d_in[1]; // [2, N] i64
    const int* cen = (const int*)d_in[2];              // [2, N] i32

    const int rows = in_sizes[1];      // 2*N
    const int N = rows / 2;

    const int npairs = rows / 2;
    int nblocks = (npairs + 255) / 256;  // ~1954
    if (nblocks > MAXP) nblocks = MAXP;

    loss_k<<<nblocks, 256>>>(preds, labs, cen, N, rows, (float*)d_out);
}

// round 16
// speedup vs baseline: 1.3421x; 1.3421x over previous
#include <cuda_runtime.h>

#define EPSF 1e-10f
#define NBLK 592

static __device__ double g_partials[NBLK];
static __device__ unsigned g_count;   // zero-init; reset by last block each launch

__global__ void __launch_bounds__(256) loss_k(
    const float* __restrict__ preds,
    const long long* __restrict__ labs,
    const int* __restrict__ cen,
    int N, int rows, float* __restrict__ out)
{
    const int tid = threadIdx.x;
    const int nthreads = gridDim.x * blockDim.x;
    double local = 0.0;

    // grid-stride over rows: each thread serially handles ~rows/nthreads rows.
    // Larger per-CTA runtime amortizes the cross-CTA L1tex-queue spread that
    // penalizes one-shot kernels with front-batched load windows.
    for (int row = blockIdx.x * blockDim.x + tid; row < rows; row += nthreads) {
        // independent scalar loads up front
        const int c = cen[row];
        const long long lself = labs[row];
        const long long l0 = (row < N) ? lself : labs[row - N];

        const float* prow = preds + (size_t)row * 100;

        if (c == 0) {
            // uncensored: log p[row, lab]
            local += (double)__logf(__ldg(prow + (int)lself) + EPSF);
        } else {
            // censored: s = sum_{j>=t1} p. Rows are softmax outputs (sum==1):
            // read the SHORTER side — suffix if t1>50 (exact, small-s safe),
            // else prefix with s = 1 - prefix (s >= ~0.5, err ~1e-7 rel).
            const int t1 = (int)l0 + 1;              // 1..100
            const bool sfx = (t1 > 50);
            const int lo4 = sfx ? (t1 >> 2) : 0;
            const int hi4 = sfx ? 25 : ((t1 + 3) >> 2);
            const int r = t1 & 3;

            const float4* p4 = (const float4*)prow;  // 400B rows -> 16B aligned
            float acc = 0.0f;
            #pragma unroll
            for (int k = 0; k < 13; ++k) {           // window length <= 13 float4s
                const int j = lo4 + k;
                float4 u = (j < hi4) ? __ldg(p4 + j)
                                     : make_float4(0.f, 0.f, 0.f, 0.f);
                if (sfx) {
                    if (j == lo4 && r) {             // head mask: drop idx < t1
                        if (r > 0) u.x = 0.f;
                        if (r > 1) u.y = 0.f;
                        if (r > 2) u.z = 0.f;
                    }
                } else {
                    if (j == hi4 - 1 && r) {         // tail mask: drop idx >= t1
                        if (r < 2) u.y = 0.f;
                        if (r < 3) u.z = 0.f;
                        u.w = 0.f;                   // r in 1..3 -> w dropped
                    }
                }
                acc += (u.x + u.y) + (u.z + u.w);
            }
            const float s = sfx ? acc : fmaxf(1.0f - acc, 0.0f);
            local += 0.5 * (double)__logf(s + EPSF);
        }
    }

    // block reduction (doubles)
    #pragma unroll
    for (int o = 16; o; o >>= 1)
        local += __shfl_down_sync(0xffffffffu, local, o);

    __shared__ double wsum[8];
    const int lane = tid & 31;
    const int wib = tid >> 5;
    if (lane == 0) wsum[wib] = local;
    __syncthreads();

    if (wib == 0) {
        double v = (lane < 8) ? wsum[lane] : 0.0;
        #pragma unroll
        for (int o = 4; o; o >>= 1)
            v += __shfl_down_sync(0xffffffffu, v, o);
        if (lane == 0) g_partials[blockIdx.x] = v;
    }

    // last-block-done final reduction (no second kernel)
    __shared__ bool isLast;
    if (tid == 0) {
        __threadfence();
        unsigned c = atomicAdd(&g_count, 1u);
        isLast = (c == gridDim.x - 1);
    }
    __syncthreads();

    if (isLast) {   // block-uniform
        double v = 0.0;
        for (int k = tid; k < (int)gridDim.x; k += blockDim.x)
            v += g_partials[k];
        #pragma unroll
        for (int o = 16; o; o >>= 1)
            v += __shfl_down_sync(0xffffffffu, v, o);
        if (lane == 0) wsum[wib] = v;
        __syncthreads();
        if (tid == 0) {
            double t = 0.0;
            #pragma unroll
            for (int w = 0; w < 8; ++w) t += wsum[w];
            *out = (float)(-t / (double)N);
            g_count = 0;                      // reset for next graph replay
        }
    }
}

extern "C" void kernel_launch(void* const* d_in, const int* in_sizes, int n_in,
                              void* d_out, int out_size)
{
    const float* preds = (const float*)d_in[0];        // [2, N, 100] f32
    const long long* labs = (const long long*)d_in[1]; // [2, N] i64
    const int* cen = (const int*)d_in[2];              // [2, N] i32

    const int rows = in_sizes[1];      // 2*N
    const int N = rows / 2;

    loss_k<<<NBLK, 256>>>(preds, labs, cen, N, rows, (float*)d_out);
}